// round 13
// baseline (speedup 1.0000x reference)
#include <cuda_runtime.h>
#include <cstdint>

#define K_TOTAL 100000
#define KC      704
#define NB      143                           // 142*704 + 32 = 100000 exactly
#define KB      32                            // k per pipeline step
#define SEQ     64
#define G4      200
#define HID     50
#define SG      (SEQ * G4)                    // 12800

#define RGROUPS 16
#define RSPAN   9                             // 16*9 = 144 >= 143

#define XROW    36                            // padded X staging row (floats)
#define STG_BYTES (25600 + 64 * 128)          // W + X per stage = 33792

// Scratch (device globals)
__device__ float g_partial[NB * SG];          // 7.3 MB
__device__ float g_p2[RGROUPS * SG];

typedef unsigned long long ull;

__device__ __forceinline__ ull pack2(float a, float b) {
    ull r; asm("mov.b64 %0, {%1, %2};" : "=l"(r) : "f"(a), "f"(b)); return r;
}
__device__ __forceinline__ void fma2(ull& d, ull a, ull b) {
    asm("fma.rn.f32x2 %0, %1, %2, %0;" : "+l"(d) : "l"(a), "l"(b));
}
__device__ __forceinline__ ull add2(ull a, ull b) {
    ull r; asm("add.rn.f32x2 %0, %1, %2;" : "=l"(r) : "l"(a), "l"(b)); return r;
}
__device__ __forceinline__ float lo32(ull v) { return __uint_as_float((unsigned)(v & 0xffffffffu)); }
__device__ __forceinline__ float hi32(ull v) { return __uint_as_float((unsigned)(v >> 32)); }

__device__ __forceinline__ uint32_t smem_u32(const void* p) {
    return (uint32_t)__cvta_generic_to_shared(p);
}
__device__ __forceinline__ void bulk_g2s(uint32_t dst, const void* src, uint32_t bytes,
                                         uint32_t mbar) {
    asm volatile(
        "cp.async.bulk.shared::cta.global.mbarrier::complete_tx::bytes [%0], [%1], %2, [%3];"
        :: "r"(dst), "l"(src), "r"(bytes), "r"(mbar) : "memory");
}
__device__ __forceinline__ void mbar_init(uint32_t mbar, uint32_t cnt) {
    asm volatile("mbarrier.init.shared.b64 [%0], %1;" :: "r"(mbar), "r"(cnt) : "memory");
}
__device__ __forceinline__ void mbar_expect(uint32_t mbar, uint32_t bytes) {
    asm volatile("mbarrier.arrive.expect_tx.shared.b64 _, [%0], %1;"
                 :: "r"(mbar), "r"(bytes) : "memory");
}
__device__ __forceinline__ void mbar_wait(uint32_t mbar, uint32_t phase) {
    asm volatile(
        "{\n\t.reg .pred P;\n\t"
        "W%=: mbarrier.try_wait.parity.acquire.cta.shared::cta.b64 P, [%0], %1, 0x989680;\n\t"
        "@P bra D%=;\n\t"
        "bra W%=;\n\t"
        "D%=:\n\t}"
        :: "r"(mbar), "r"(phase) : "memory");
}

__device__ __forceinline__ uint32_t cvtpack(float hi_val, float lo_val) {
    uint32_t r;
    asm("cvt.rn.bf16x2.f32 %0, %1, %2;" : "=r"(r) : "f"(hi_val), "f"(lo_val));
    return r;
}

__device__ __forceinline__ void mma16816(float* d,
                                         uint32_t a0, uint32_t a1, uint32_t a2, uint32_t a3,
                                         uint32_t b0, uint32_t b1) {
    asm volatile(
        "mma.sync.aligned.m16n8k16.row.col.f32.bf16.bf16.f32 "
        "{%0,%1,%2,%3}, {%4,%5,%6,%7}, {%8,%9}, {%0,%1,%2,%3};"
        : "+f"(d[0]), "+f"(d[1]), "+f"(d[2]), "+f"(d[3])
        : "r"(a0), "r"(a1), "r"(a2), "r"(a3), "r"(b0), "r"(b1));
}

// mslot(j) for j in 0..7 (compile-time table): 2*(j&3) + (j>>2)
__device__ __constant__ const int MSJ[8] = {0, 2, 4, 6, 1, 3, 5, 7};

// ---------------------------------------------------------------------------
// Phase A: split-K tensor-core GEMM (bf16 split precision, 3 combos).
// 143 CTAs x 512 threads. 4-stage BULK-copy staging (1 W bulk + 64 X row
// bulks per stage -> 65 LSU ops instead of 2112 cp.asyncs), mbarrier-gated.
// Warp mapping: 2 m-groups x 8 n-groups.
// ---------------------------------------------------------------------------
__global__ void __launch_bounds__(512, 1) gemm_partial(
    const float* __restrict__ x, const float* __restrict__ Wi)
{
    extern __shared__ float sm[];
    // layout: [mbar 4x8B = 8 floats][stgX 4x64x36][stgW 4x6400][conv bufs]
    ull*   mbars = (ull*)sm;                                // 4 mbarriers
    float* stgX = sm + 16;                                  // 4 x 64x36 f32
    float* stgW = stgX + 4 * (64 * XROW);                   // 4 x 32x200 f32
    uint32_t* cXh = (uint32_t*)(stgW + 4 * 6400);           // 2 x 64x18 b32
    uint32_t* cXl = cXh + 2 * 1152;
    uint32_t* cWh = cXl + 2 * 1152;                         // 2 x 200x18 b32
    uint32_t* cWl = cWh + 2 * 3600;

    const int t  = threadIdx.x;
    const int k0 = blockIdx.x * KC;
    const int kcnt = (K_TOTAL - k0 < KC) ? (K_TOTAL - k0) : KC;
    const int S = kcnt / KB;                                // 22 or 1

    const int warp = t >> 5, lane = t & 31;
    const int g = lane >> 2, tq = lane & 3;
    const int mg = warp >> 3;                               // 0..1 (2 m-tiles each)
    const int ng = warp & 7;                                // 0..7
    const int NT   = (ng == 0) ? 4 : 3;
    const int nbeg = (ng == 0) ? 0 : (4 + 3 * (ng - 1));    // 4+7*3 = 25 tiles

    if (t == 0) {
        #pragma unroll
        for (int b = 0; b < 4; b++) mbar_init(smem_u32(&mbars[b]), 1);
    }
    __syncthreads();

    float acc[2][4][4];
    #pragma unroll
    for (int a = 0; a < 2; a++)
        #pragma unroll
        for (int b = 0; b < 4; b++)
            #pragma unroll
            for (int c = 0; c < 4; c++) acc[a][b][c] = 0.f;

    auto issue_stage = [&](int step) {
        const int b4 = step & 3;
        const int kg = k0 + step * KB;
        const uint32_t mb = smem_u32(&mbars[b4]);
        if (t == 0) {
            mbar_expect(mb, STG_BYTES);
            bulk_g2s(smem_u32(stgW + b4 * 6400), Wi + (size_t)kg * G4, 25600, mb);
        }
        if (t < 64) {
            bulk_g2s(smem_u32(stgX + b4 * (64 * XROW) + t * XROW),
                     x + (size_t)t * K_TOTAL + kg, 128, mb);
        }
    };

    auto wait_stage = [&](int step) {
        mbar_wait(smem_u32(&mbars[step & 3]), (step >> 2) & 1);
    };

    auto convert = [&](int b4, int b2) {
        // W: threads 0..399, n0 = t%200, half = t/200, 8 k-pairs each.
        if (t < 400) {
            const int n0 = t % 200;
            const int half = t / 200;
            const float* sWb = stgW + b4 * 6400 + half * 3200 + n0;
            uint32_t* whb = cWh + b2 * 3600 + n0 * 18 + half * 8;
            uint32_t* wlb = cWl + b2 * 3600 + n0 * 18 + half * 8;
            #pragma unroll
            for (int j = 0; j < 8; j++) {
                const float f0 = sWb[400 * j];
                const float f1 = sWb[400 * j + 200];
                const uint32_t hi = cvtpack(f1, f0);
                const float h0 = __uint_as_float(hi << 16);
                const float h1 = __uint_as_float(hi & 0xFFFF0000u);
                const uint32_t lo = cvtpack(f1 - h1, f0 - h0);
                whb[MSJ[j]] = hi;
                wlb[MSJ[j]] = lo;
            }
        }
        // X: threads 256..511, row = tx>>2, quarter q = tx&3, 4 k-pairs each.
        if (t >= 256) {
            const int tx = t - 256;
            const int row = tx >> 2, q = tx & 3;
            const float* sXb = stgX + b4 * (64 * XROW) + row * XROW + 8 * q;
            const int mbase = (q >> 1) * 8 + (q & 1);
            uint32_t* xhb = cXh + b2 * 1152 + row * 18 + mbase;
            uint32_t* xlb = cXl + b2 * 1152 + row * 18 + mbase;
            #pragma unroll
            for (int j = 0; j < 4; j++) {
                const float f0 = sXb[2 * j];
                const float f1 = sXb[2 * j + 1];
                const uint32_t hi = cvtpack(f1, f0);
                const float h0 = __uint_as_float(hi << 16);
                const float h1 = __uint_as_float(hi & 0xFFFF0000u);
                const uint32_t lo = cvtpack(f1 - h1, f0 - h0);
                xhb[2 * j] = hi;
                xlb[2 * j] = lo;
            }
        }
    };

    auto mma_tile = [&](int b2) {
        const uint32_t* xh = cXh + b2 * 1152; const uint32_t* xl = cXl + b2 * 1152;
        const uint32_t* wh = cWh + b2 * 3600; const uint32_t* wl = cWl + b2 * 3600;
        #pragma unroll
        for (int kb = 0; kb < 16; kb += 8) {
            uint2 Ah0[2], Ah1[2], Al0[2], Al1[2];
            #pragma unroll
            for (int m2 = 0; m2 < 2; m2++) {
                const int r0 = (mg * 2 + m2) * 16 + g;
                Ah0[m2] = *(const uint2*)(xh + r0 * 18 + kb + 2 * tq);
                Ah1[m2] = *(const uint2*)(xh + (r0 + 8) * 18 + kb + 2 * tq);
                Al0[m2] = *(const uint2*)(xl + r0 * 18 + kb + 2 * tq);
                Al1[m2] = *(const uint2*)(xl + (r0 + 8) * 18 + kb + 2 * tq);
            }
            #pragma unroll
            for (int i = 0; i < 4; i++) {
                if (i < NT) {
                    const int n = (nbeg + i) * 8 + g;
                    const uint2 Bh = *(const uint2*)(wh + n * 18 + kb + 2 * tq);
                    const uint2 Bl = *(const uint2*)(wl + n * 18 + kb + 2 * tq);
                    #pragma unroll
                    for (int m2 = 0; m2 < 2; m2++) {
                        mma16816(acc[m2][i], Ah0[m2].x, Ah1[m2].x, Ah0[m2].y, Ah1[m2].y, Bh.x, Bh.y);
                        mma16816(acc[m2][i], Ah0[m2].x, Ah1[m2].x, Ah0[m2].y, Ah1[m2].y, Bl.x, Bl.y);
                        mma16816(acc[m2][i], Al0[m2].x, Al1[m2].x, Al0[m2].y, Al1[m2].y, Bh.x, Bh.y);
                    }
                }
            }
        }
    };

    // ---- pipeline (4 buffers, prefetch depth 3) ----
    issue_stage(0);
    if (S > 1) issue_stage(1);
    if (S > 2) issue_stage(2);
    wait_stage(0);
    __syncthreads();
    convert(0, 0);

    for (int s = 0; s < S; s++) {
        if (s + 3 < S) issue_stage(s + 3);
        if (s + 1 < S) wait_stage(s + 1);
        __syncthreads();        // publishes convert(s) for mma; stage s+1 visible
        if (s + 1 < S) convert((s + 1) & 3, (s + 1) & 1);
        mma_tile(s & 1);
    }

    // ---- epilogue ----
    float* pout = g_partial + (size_t)blockIdx.x * SG;
    #pragma unroll
    for (int m2 = 0; m2 < 2; m2++) {
        const int r0 = (mg * 2 + m2) * 16 + g;
        #pragma unroll
        for (int i = 0; i < 4; i++) {
            if (i < NT) {
                const int col = (nbeg + i) * 8 + 2 * tq;
                *(float2*)(pout + (size_t)r0 * G4 + col)       = make_float2(acc[m2][i][0], acc[m2][i][1]);
                *(float2*)(pout + (size_t)(r0 + 8) * G4 + col) = make_float2(acc[m2][i][2], acc[m2][i][3]);
            }
        }
    }
}

// ---------------------------------------------------------------------------
// Phase B: stage-1 split-K reduce (143 -> 16)
// ---------------------------------------------------------------------------
__global__ void reduce_stage1()
{
    const int idx = blockIdx.x * blockDim.x + threadIdx.x;
    const int grp = blockIdx.y;
    if (idx >= SG) return;
    const int b0   = grp * RSPAN;
    const int bend = (b0 + RSPAN < NB) ? (b0 + RSPAN) : NB;
    float s0 = 0.f, s1 = 0.f, s2 = 0.f, s3 = 0.f;
    int b = b0;
    for (; b + 3 < bend; b += 4) {
        s0 += g_partial[(size_t)(b + 0) * SG + idx];
        s1 += g_partial[(size_t)(b + 1) * SG + idx];
        s2 += g_partial[(size_t)(b + 2) * SG + idx];
        s3 += g_partial[(size_t)(b + 3) * SG + idx];
    }
    for (; b < bend; b++) s0 += g_partial[(size_t)b * SG + idx];
    g_p2[(size_t)grp * SG + idx] = (s0 + s1) + (s2 + s3);
}

// ---------------------------------------------------------------------------
// Phase C: LSTM producer/consumer with bar.arrive / bar.sync (round-12 best).
// ---------------------------------------------------------------------------
__device__ __forceinline__ float tanh_fast(float v) {
    float r; asm("tanh.approx.f32 %0, %1;" : "=f"(r) : "f"(v)); return r;
}
__device__ __forceinline__ float sig_fast(float v) {
    return fmaf(0.5f, tanh_fast(0.5f * v), 0.5f);
}

__global__ void __launch_bounds__(256) lstm_kernel(const float* __restrict__ Wh,
                                                   const float* __restrict__ bi,
                                                   const float* __restrict__ bh,
                                                   float* __restrict__ out)
{
    extern __shared__ float sml[];
    float* gates_s = sml;                 // SG floats
    float* hbuf    = sml + SG;            // 64 floats (16B aligned)
    float* gbuf    = hbuf + 64;           // 200 floats
    const int t = threadIdx.x;

    // merged reduce (16 partials) + biases -> gates_s (all 8 warps)
    {
        const float4* src = (const float4*)g_p2;
        float4* dst = (float4*)gates_s;
        for (int i4 = t; i4 < SG / 4; i4 += 256) {
            float4 a0 = make_float4(0.f, 0.f, 0.f, 0.f);
            float4 a1 = a0, a2 = a0, a3 = a0;
            #pragma unroll
            for (int b = 0; b < RGROUPS; b += 4) {
                float4 v0 = src[(size_t)(b + 0) * (SG / 4) + i4];
                float4 v1 = src[(size_t)(b + 1) * (SG / 4) + i4];
                float4 v2 = src[(size_t)(b + 2) * (SG / 4) + i4];
                float4 v3 = src[(size_t)(b + 3) * (SG / 4) + i4];
                a0.x += v0.x; a0.y += v0.y; a0.z += v0.z; a0.w += v0.w;
                a1.x += v1.x; a1.y += v1.y; a1.z += v1.z; a1.w += v1.w;
                a2.x += v2.x; a2.y += v2.y; a2.z += v2.z; a2.w += v2.w;
                a3.x += v3.x; a3.y += v3.y; a3.z += v3.z; a3.w += v3.w;
            }
            const int gbase = (i4 * 4) % G4;
            const float4 bv1 = *(const float4*)(bi + gbase);
            const float4 bv2 = *(const float4*)(bh + gbase);
            float4 r;
            r.x = (a0.x + a1.x) + (a2.x + a3.x) + bv1.x + bv2.x;
            r.y = (a0.y + a1.y) + (a2.y + a3.y) + bv1.y + bv2.y;
            r.z = (a0.z + a1.z) + (a2.z + a3.z) + bv1.z + bv2.z;
            r.w = (a0.w + a1.w) + (a2.w + a3.w) + bv1.w + bv2.w;
            dst[i4] = r;
        }
    }

    ull wp[25];
    if (t < G4) {
        #pragma unroll
        for (int kk = 0; kk < 25; kk++) {
            float w0 = Wh[(2 * kk + 0) * G4 + t];
            float w1 = Wh[(2 * kk + 1) * G4 + t];
            wp[kk] = pack2(w0, w1);
        }
    }
    if (t < 64) hbuf[t] = 0.f;
    __syncthreads();

    if (t < 224) {
        // producers (warps 0-6)
        for (int step = 0; step < SEQ; step++) {
            if (step > 0)
                asm volatile("bar.sync 2, 256;" ::: "memory");
            if (t < G4) {
                const float pre = gates_s[step * G4 + t];
                ull a0 = 0ull, a1 = 0ull, a2 = 0ull, a3 = 0ull;
                #pragma unroll
                for (int kk = 0; kk < 24; kk += 4) {
                    const ull h0 = *(const ull*)(hbuf + 2 * kk);
                    const ull h1 = *(const ull*)(hbuf + 2 * kk + 2);
                    const ull h2 = *(const ull*)(hbuf + 2 * kk + 4);
                    const ull h3 = *(const ull*)(hbuf + 2 * kk + 6);
                    fma2(a0, h0, wp[kk]);
                    fma2(a1, h1, wp[kk + 1]);
                    fma2(a2, h2, wp[kk + 2]);
                    fma2(a3, h3, wp[kk + 3]);
                }
                fma2(a0, *(const ull*)(hbuf + 48), wp[24]);
                const ull s = add2(add2(a0, a1), add2(a2, a3));
                gbuf[t] = pre + lo32(s) + hi32(s);
            }
            asm volatile("bar.arrive 1, 256;" ::: "memory");
        }
    } else {
        // consumer (warp 7)
        const int l = t - 224;
        float c0 = 0.f, c1 = 0.f, h0 = 0.f, h1 = 0.f;
        for (int step = 0; step < SEQ; step++) {
            asm volatile("bar.sync 1, 256;" ::: "memory");
            if (l < 25) {
                const int uA = l, uB = l + 25;
                const float iA = sig_fast(gbuf[uA]);
                const float fA = sig_fast(gbuf[50 + uA]);
                const float gA = tanh_fast(gbuf[100 + uA]);
                const float oA = sig_fast(gbuf[150 + uA]);
                const float iB = sig_fast(gbuf[uB]);
                const float fB = sig_fast(gbuf[50 + uB]);
                const float gB = tanh_fast(gbuf[100 + uB]);
                const float oB = sig_fast(gbuf[150 + uB]);
                c0 = fA * c0 + iA * gA;
                c1 = fB * c1 + iB * gB;
                h0 = oA * tanh_fast(c0);
                h1 = oB * tanh_fast(c1);
                hbuf[uA] = h0;
                hbuf[uB] = h1;
            }
            asm volatile("bar.arrive 2, 256;" ::: "memory");
        }
        if (l < 25) { out[l] = h0; out[l + 25] = h1; }
    }
}

// ---------------------------------------------------------------------------
extern "C" void kernel_launch(void* const* d_in, const int* in_sizes, int n_in,
                              void* d_out, int out_size)
{
    const float* x  = (const float*)d_in[0];
    const float* Wi = (const float*)d_in[1];
    const float* bi = (const float*)d_in[2];
    const float* Wh = (const float*)d_in[3];
    const float* bh = (const float*)d_in[4];
    float* out = (float*)d_out;

    (void)in_sizes; (void)n_in; (void)out_size;

    const int gemm_smem = 16 * 4 + 4 * 64 * XROW * 4 + 4 * 6400 * 4
                        + (2 * 1152 * 2 + 2 * 3600 * 2) * 4;   // ~215.4 KB
    cudaFuncSetAttribute(gemm_partial, cudaFuncAttributeMaxDynamicSharedMemorySize,
                         gemm_smem);
    const int lstm_smem = (SG + 64 + 200) * 4 + 64;
    cudaFuncSetAttribute(lstm_kernel, cudaFuncAttributeMaxDynamicSharedMemorySize,
                         lstm_smem);

    gemm_partial<<<NB, 512, gemm_smem>>>(x, Wi);
    reduce_stage1<<<dim3(SG / 128, RGROUPS), 128>>>();
    lstm_kernel<<<1, 256, lstm_smem>>>(Wh, bi, bh, out);
}

// round 14
// speedup vs baseline: 1.2130x; 1.2130x over previous
#include <cuda_runtime.h>
#include <cstdint>

#define K_TOTAL 100000
#define KC      704
#define NB      143                           // 142*704 + 32 = 100000 exactly
#define KB      32                            // k per pipeline step
#define SEQ     64
#define G4      200
#define HID     50
#define SG      (SEQ * G4)                    // 12800

#define RGROUPS 16
#define RSPAN   9                             // 16*9 = 144 >= 143

#define XROW    36                            // padded X staging row (floats)

// Scratch (device globals)
__device__ float g_partial[NB * SG];          // 7.3 MB
__device__ float g_p2[RGROUPS * SG];

typedef unsigned long long ull;

__device__ __forceinline__ ull pack2(float a, float b) {
    ull r; asm("mov.b64 %0, {%1, %2};" : "=l"(r) : "f"(a), "f"(b)); return r;
}
__device__ __forceinline__ void fma2(ull& d, ull a, ull b) {
    asm("fma.rn.f32x2 %0, %1, %2, %0;" : "+l"(d) : "l"(a), "l"(b));
}
__device__ __forceinline__ ull add2(ull a, ull b) {
    ull r; asm("add.rn.f32x2 %0, %1, %2;" : "=l"(r) : "l"(a), "l"(b)); return r;
}
__device__ __forceinline__ float lo32(ull v) { return __uint_as_float((unsigned)(v & 0xffffffffu)); }
__device__ __forceinline__ float hi32(ull v) { return __uint_as_float((unsigned)(v >> 32)); }

__device__ __forceinline__ uint32_t smem_u32(const void* p) {
    return (uint32_t)__cvta_generic_to_shared(p);
}
__device__ __forceinline__ void cp_async16(float* smem, const float* gmem) {
    unsigned sa = (unsigned)__cvta_generic_to_shared(smem);
    asm volatile("cp.async.cg.shared.global [%0], [%1], 16;" :: "r"(sa), "l"(gmem));
}
__device__ __forceinline__ void cp_commit() { asm volatile("cp.async.commit_group;"); }
__device__ __forceinline__ void cp_wait2() { asm volatile("cp.async.wait_group 2;"); }

__device__ __forceinline__ void bulk_g2s(uint32_t dst, const void* src, uint32_t bytes,
                                         uint32_t mbar) {
    asm volatile(
        "cp.async.bulk.shared::cta.global.mbarrier::complete_tx::bytes [%0], [%1], %2, [%3];"
        :: "r"(dst), "l"(src), "r"(bytes), "r"(mbar) : "memory");
}
__device__ __forceinline__ void mbar_init(uint32_t mbar, uint32_t cnt) {
    asm volatile("mbarrier.init.shared.b64 [%0], %1;" :: "r"(mbar), "r"(cnt) : "memory");
}
__device__ __forceinline__ void mbar_expect(uint32_t mbar, uint32_t bytes) {
    asm volatile("mbarrier.arrive.expect_tx.shared.b64 _, [%0], %1;"
                 :: "r"(mbar), "r"(bytes) : "memory");
}
__device__ __forceinline__ void mbar_wait(uint32_t mbar, uint32_t phase) {
    asm volatile(
        "{\n\t.reg .pred P;\n\t"
        "W%=: mbarrier.try_wait.parity.acquire.cta.shared::cta.b64 P, [%0], %1, 0x989680;\n\t"
        "@P bra D%=;\n\t"
        "bra W%=;\n\t"
        "D%=:\n\t}"
        :: "r"(mbar), "r"(phase) : "memory");
}

__device__ __forceinline__ uint32_t cvtpack(float hi_val, float lo_val) {
    uint32_t r;
    asm("cvt.rn.bf16x2.f32 %0, %1, %2;" : "=r"(r) : "f"(hi_val), "f"(lo_val));
    return r;
}

__device__ __forceinline__ void mma16816(float* d,
                                         uint32_t a0, uint32_t a1, uint32_t a2, uint32_t a3,
                                         uint32_t b0, uint32_t b1) {
    asm volatile(
        "mma.sync.aligned.m16n8k16.row.col.f32.bf16.bf16.f32 "
        "{%0,%1,%2,%3}, {%4,%5,%6,%7}, {%8,%9}, {%0,%1,%2,%3};"
        : "+f"(d[0]), "+f"(d[1]), "+f"(d[2]), "+f"(d[3])
        : "r"(a0), "r"(a1), "r"(a2), "r"(a3), "r"(b0), "r"(b1));
}

// mslot(j) for j in 0..7 (compile-time table): 2*(j&3) + (j>>2)
__device__ __constant__ const int MSJ[8] = {0, 2, 4, 6, 1, 3, 5, 7};

// ---------------------------------------------------------------------------
// Phase A: split-K tensor-core GEMM (bf16 split precision, 3 combos).
// 143 CTAs x 512 threads. HYBRID staging: W = ONE 25.6KB bulk/stage (mbarrier),
// X = 512 cp.async/stage (wait_group). LSU ops/stage 2112 -> ~515.
// Warp mapping: 2 m-groups x 8 n-groups. 4 stage buffers, prefetch depth 3.
// ---------------------------------------------------------------------------
__global__ void __launch_bounds__(512, 1) gemm_partial(
    const float* __restrict__ x, const float* __restrict__ Wi)
{
    extern __shared__ float sm[];
    // layout: [mbars 4x8B][stgX 4x64x36][stgW 4x6400][conv bufs]
    ull*   mbars = (ull*)sm;
    float* stgX = sm + 16;                                  // 4 x 64x36 f32
    float* stgW = stgX + 4 * (64 * XROW);                   // 4 x 32x200 f32
    uint32_t* cXh = (uint32_t*)(stgW + 4 * 6400);           // 2 x 64x18 b32
    uint32_t* cXl = cXh + 2 * 1152;
    uint32_t* cWh = cXl + 2 * 1152;                         // 2 x 200x18 b32
    uint32_t* cWl = cWh + 2 * 3600;

    const int t  = threadIdx.x;
    const int k0 = blockIdx.x * KC;
    const int kcnt = (K_TOTAL - k0 < KC) ? (K_TOTAL - k0) : KC;
    const int S = kcnt / KB;                                // 22 or 1

    const int warp = t >> 5, lane = t & 31;
    const int g = lane >> 2, tq = lane & 3;
    const int mg = warp >> 3;                               // 0..1 (2 m-tiles each)
    const int ng = warp & 7;                                // 0..7
    const int NT   = (ng == 0) ? 4 : 3;
    const int nbeg = (ng == 0) ? 0 : (4 + 3 * (ng - 1));    // 25 n-tiles total

    if (t == 0) {
        #pragma unroll
        for (int b = 0; b < 4; b++) mbar_init(smem_u32(&mbars[b]), 1);
    }
    __syncthreads();

    float acc[2][4][4];
    #pragma unroll
    for (int a = 0; a < 2; a++)
        #pragma unroll
        for (int b = 0; b < 4; b++)
            #pragma unroll
            for (int c = 0; c < 4; c++) acc[a][b][c] = 0.f;

    // W: one bulk per stage (thread 0). X: 512 cp.async slots.
    auto issue_stage = [&](int step) {
        const int b4 = step & 3;
        const int kg = k0 + step * KB;
        if (t == 0) {
            const uint32_t mb = smem_u32(&mbars[b4]);
            mbar_expect(mb, 25600);
            bulk_g2s(smem_u32(stgW + b4 * 6400), Wi + (size_t)kg * G4, 25600, mb);
        }
        {   // X: row = t>>3, quad = t&7
            float* dX = stgX + b4 * (64 * XROW);
            const int row = t >> 3, q = t & 7;
            cp_async16(dX + row * XROW + q * 4, x + (size_t)row * K_TOTAL + kg + q * 4);
        }
    };

    auto wait_W = [&](int step) {
        mbar_wait(smem_u32(&mbars[step & 3]), (step >> 2) & 1);
    };

    auto convert = [&](int b4, int b2) {
        // W: threads 0..399, n0 = t%200, half = t/200, 8 k-pairs each.
        if (t < 400) {
            const int n0 = t % 200;
            const int half = t / 200;
            const float* sWb = stgW + b4 * 6400 + half * 3200 + n0;
            uint32_t* whb = cWh + b2 * 3600 + n0 * 18 + half * 8;
            uint32_t* wlb = cWl + b2 * 3600 + n0 * 18 + half * 8;
            #pragma unroll
            for (int j = 0; j < 8; j++) {
                const float f0 = sWb[400 * j];
                const float f1 = sWb[400 * j + 200];
                const uint32_t hi = cvtpack(f1, f0);
                const float h0 = __uint_as_float(hi << 16);
                const float h1 = __uint_as_float(hi & 0xFFFF0000u);
                const uint32_t lo = cvtpack(f1 - h1, f0 - h0);
                whb[MSJ[j]] = hi;
                wlb[MSJ[j]] = lo;
            }
        }
        // X: threads 256..511, row = tx>>2, quarter q = tx&3, 4 k-pairs each.
        if (t >= 256) {
            const int tx = t - 256;
            const int row = tx >> 2, q = tx & 3;
            const float* sXb = stgX + b4 * (64 * XROW) + row * XROW + 8 * q;
            const int mbase = (q >> 1) * 8 + (q & 1);
            uint32_t* xhb = cXh + b2 * 1152 + row * 18 + mbase;
            uint32_t* xlb = cXl + b2 * 1152 + row * 18 + mbase;
            #pragma unroll
            for (int j = 0; j < 4; j++) {
                const float f0 = sXb[2 * j];
                const float f1 = sXb[2 * j + 1];
                const uint32_t hi = cvtpack(f1, f0);
                const float h0 = __uint_as_float(hi << 16);
                const float h1 = __uint_as_float(hi & 0xFFFF0000u);
                const uint32_t lo = cvtpack(f1 - h1, f0 - h0);
                xhb[2 * j] = hi;
                xlb[2 * j] = lo;
            }
        }
    };

    auto mma_tile = [&](int b2) {
        const uint32_t* xh = cXh + b2 * 1152; const uint32_t* xl = cXl + b2 * 1152;
        const uint32_t* wh = cWh + b2 * 3600; const uint32_t* wl = cWl + b2 * 3600;
        #pragma unroll
        for (int kb = 0; kb < 16; kb += 8) {
            uint2 Ah0[2], Ah1[2], Al0[2], Al1[2];
            #pragma unroll
            for (int m2 = 0; m2 < 2; m2++) {
                const int r0 = (mg * 2 + m2) * 16 + g;
                Ah0[m2] = *(const uint2*)(xh + r0 * 18 + kb + 2 * tq);
                Ah1[m2] = *(const uint2*)(xh + (r0 + 8) * 18 + kb + 2 * tq);
                Al0[m2] = *(const uint2*)(xl + r0 * 18 + kb + 2 * tq);
                Al1[m2] = *(const uint2*)(xl + (r0 + 8) * 18 + kb + 2 * tq);
            }
            #pragma unroll
            for (int i = 0; i < 4; i++) {
                if (i < NT) {
                    const int n = (nbeg + i) * 8 + g;
                    const uint2 Bh = *(const uint2*)(wh + n * 18 + kb + 2 * tq);
                    const uint2 Bl = *(const uint2*)(wl + n * 18 + kb + 2 * tq);
                    #pragma unroll
                    for (int m2 = 0; m2 < 2; m2++) {
                        mma16816(acc[m2][i], Ah0[m2].x, Ah1[m2].x, Ah0[m2].y, Ah1[m2].y, Bh.x, Bh.y);
                        mma16816(acc[m2][i], Ah0[m2].x, Ah1[m2].x, Ah0[m2].y, Ah1[m2].y, Bl.x, Bl.y);
                        mma16816(acc[m2][i], Al0[m2].x, Al1[m2].x, Al0[m2].y, Al1[m2].y, Bh.x, Bh.y);
                    }
                }
            }
        }
    };

    // ---- pipeline (4 buffers, prefetch depth 3) ----
    issue_stage(0);
    cp_commit();
    if (S > 1) issue_stage(1);
    cp_commit();
    if (S > 2) issue_stage(2);
    cp_commit();
    cp_wait2();                 // X stage 0 landed (this thread)
    wait_W(0);                  // W stage 0 landed
    __syncthreads();            // everyone's X0 visible
    convert(0, 0);

    for (int s = 0; s < S; s++) {
        if (s + 3 < S) issue_stage(s + 3);
        cp_commit();
        cp_wait2();             // own X(s+1) drained
        if (s + 1 < S) wait_W(s + 1);
        __syncthreads();        // X(s+1) all-visible; convert(s) published for mma
        if (s + 1 < S) convert((s + 1) & 3, (s + 1) & 1);
        mma_tile(s & 1);
    }

    // ---- epilogue ----
    float* pout = g_partial + (size_t)blockIdx.x * SG;
    #pragma unroll
    for (int m2 = 0; m2 < 2; m2++) {
        const int r0 = (mg * 2 + m2) * 16 + g;
        #pragma unroll
        for (int i = 0; i < 4; i++) {
            if (i < NT) {
                const int col = (nbeg + i) * 8 + 2 * tq;
                *(float2*)(pout + (size_t)r0 * G4 + col)       = make_float2(acc[m2][i][0], acc[m2][i][1]);
                *(float2*)(pout + (size_t)(r0 + 8) * G4 + col) = make_float2(acc[m2][i][2], acc[m2][i][3]);
            }
        }
    }
}

// ---------------------------------------------------------------------------
// Phase B: stage-1 split-K reduce (143 -> 16)
// ---------------------------------------------------------------------------
__global__ void reduce_stage1()
{
    const int idx = blockIdx.x * blockDim.x + threadIdx.x;
    const int grp = blockIdx.y;
    if (idx >= SG) return;
    const int b0   = grp * RSPAN;
    const int bend = (b0 + RSPAN < NB) ? (b0 + RSPAN) : NB;
    float s0 = 0.f, s1 = 0.f, s2 = 0.f, s3 = 0.f;
    int b = b0;
    for (; b + 3 < bend; b += 4) {
        s0 += g_partial[(size_t)(b + 0) * SG + idx];
        s1 += g_partial[(size_t)(b + 1) * SG + idx];
        s2 += g_partial[(size_t)(b + 2) * SG + idx];
        s3 += g_partial[(size_t)(b + 3) * SG + idx];
    }
    for (; b < bend; b++) s0 += g_partial[(size_t)b * SG + idx];
    g_p2[(size_t)grp * SG + idx] = (s0 + s1) + (s2 + s3);
}

// ---------------------------------------------------------------------------
// Phase C: LSTM producer/consumer with bar.arrive / bar.sync (round-12 best).
// ---------------------------------------------------------------------------
__device__ __forceinline__ float tanh_fast(float v) {
    float r; asm("tanh.approx.f32 %0, %1;" : "=f"(r) : "f"(v)); return r;
}
__device__ __forceinline__ float sig_fast(float v) {
    return fmaf(0.5f, tanh_fast(0.5f * v), 0.5f);
}

__global__ void __launch_bounds__(256) lstm_kernel(const float* __restrict__ Wh,
                                                   const float* __restrict__ bi,
                                                   const float* __restrict__ bh,
                                                   float* __restrict__ out)
{
    extern __shared__ float sml[];
    float* gates_s = sml;                 // SG floats
    float* hbuf    = sml + SG;            // 64 floats (16B aligned)
    float* gbuf    = hbuf + 64;           // 200 floats
    const int t = threadIdx.x;

    // merged reduce (16 partials) + biases -> gates_s (all 8 warps)
    {
        const float4* src = (const float4*)g_p2;
        float4* dst = (float4*)gates_s;
        for (int i4 = t; i4 < SG / 4; i4 += 256) {
            float4 a0 = make_float4(0.f, 0.f, 0.f, 0.f);
            float4 a1 = a0, a2 = a0, a3 = a0;
            #pragma unroll
            for (int b = 0; b < RGROUPS; b += 4) {
                float4 v0 = src[(size_t)(b + 0) * (SG / 4) + i4];
                float4 v1 = src[(size_t)(b + 1) * (SG / 4) + i4];
                float4 v2 = src[(size_t)(b + 2) * (SG / 4) + i4];
                float4 v3 = src[(size_t)(b + 3) * (SG / 4) + i4];
                a0.x += v0.x; a0.y += v0.y; a0.z += v0.z; a0.w += v0.w;
                a1.x += v1.x; a1.y += v1.y; a1.z += v1.z; a1.w += v1.w;
                a2.x += v2.x; a2.y += v2.y; a2.z += v2.z; a2.w += v2.w;
                a3.x += v3.x; a3.y += v3.y; a3.z += v3.z; a3.w += v3.w;
            }
            const int gbase = (i4 * 4) % G4;
            const float4 bv1 = *(const float4*)(bi + gbase);
            const float4 bv2 = *(const float4*)(bh + gbase);
            float4 r;
            r.x = (a0.x + a1.x) + (a2.x + a3.x) + bv1.x + bv2.x;
            r.y = (a0.y + a1.y) + (a2.y + a3.y) + bv1.y + bv2.y;
            r.z = (a0.z + a1.z) + (a2.z + a3.z) + bv1.z + bv2.z;
            r.w = (a0.w + a1.w) + (a2.w + a3.w) + bv1.w + bv2.w;
            dst[i4] = r;
        }
    }

    ull wp[25];
    if (t < G4) {
        #pragma unroll
        for (int kk = 0; kk < 25; kk++) {
            float w0 = Wh[(2 * kk + 0) * G4 + t];
            float w1 = Wh[(2 * kk + 1) * G4 + t];
            wp[kk] = pack2(w0, w1);
        }
    }
    if (t < 64) hbuf[t] = 0.f;
    __syncthreads();

    if (t < 224) {
        // producers (warps 0-6)
        for (int step = 0; step < SEQ; step++) {
            if (step > 0)
                asm volatile("bar.sync 2, 256;" ::: "memory");
            if (t < G4) {
                const float pre = gates_s[step * G4 + t];
                ull a0 = 0ull, a1 = 0ull, a2 = 0ull, a3 = 0ull;
                #pragma unroll
                for (int kk = 0; kk < 24; kk += 4) {
                    const ull h0 = *(const ull*)(hbuf + 2 * kk);
                    const ull h1 = *(const ull*)(hbuf + 2 * kk + 2);
                    const ull h2 = *(const ull*)(hbuf + 2 * kk + 4);
                    const ull h3 = *(const ull*)(hbuf + 2 * kk + 6);
                    fma2(a0, h0, wp[kk]);
                    fma2(a1, h1, wp[kk + 1]);
                    fma2(a2, h2, wp[kk + 2]);
                    fma2(a3, h3, wp[kk + 3]);
                }
                fma2(a0, *(const ull*)(hbuf + 48), wp[24]);
                const ull s = add2(add2(a0, a1), add2(a2, a3));
                gbuf[t] = pre + lo32(s) + hi32(s);
            }
            asm volatile("bar.arrive 1, 256;" ::: "memory");
        }
    } else {
        // consumer (warp 7)
        const int l = t - 224;
        float c0 = 0.f, c1 = 0.f, h0 = 0.f, h1 = 0.f;
        for (int step = 0; step < SEQ; step++) {
            asm volatile("bar.sync 1, 256;" ::: "memory");
            if (l < 25) {
                const int uA = l, uB = l + 25;
                const float iA = sig_fast(gbuf[uA]);
                const float fA = sig_fast(gbuf[50 + uA]);
                const float gA = tanh_fast(gbuf[100 + uA]);
                const float oA = sig_fast(gbuf[150 + uA]);
                const float iB = sig_fast(gbuf[uB]);
                const float fB = sig_fast(gbuf[50 + uB]);
                const float gB = tanh_fast(gbuf[100 + uB]);
                const float oB = sig_fast(gbuf[150 + uB]);
                c0 = fA * c0 + iA * gA;
                c1 = fB * c1 + iB * gB;
                h0 = oA * tanh_fast(c0);
                h1 = oB * tanh_fast(c1);
                hbuf[uA] = h0;
                hbuf[uB] = h1;
            }
            asm volatile("bar.arrive 2, 256;" ::: "memory");
        }
        if (l < 25) { out[l] = h0; out[l + 25] = h1; }
    }
}

// ---------------------------------------------------------------------------
extern "C" void kernel_launch(void* const* d_in, const int* in_sizes, int n_in,
                              void* d_out, int out_size)
{
    const float* x  = (const float*)d_in[0];
    const float* Wi = (const float*)d_in[1];
    const float* bi = (const float*)d_in[2];
    const float* Wh = (const float*)d_in[3];
    const float* bh = (const float*)d_in[4];
    float* out = (float*)d_out;

    (void)in_sizes; (void)n_in; (void)out_size;

    const int gemm_smem = 16 * 4 + 4 * 64 * XROW * 4 + 4 * 6400 * 4
                        + (2 * 1152 * 2 + 2 * 3600 * 2) * 4;   // ~215.4 KB
    cudaFuncSetAttribute(gemm_partial, cudaFuncAttributeMaxDynamicSharedMemorySize,
                         gemm_smem);
    const int lstm_smem = (SG + 64 + 200) * 4 + 64;
    cudaFuncSetAttribute(lstm_kernel, cudaFuncAttributeMaxDynamicSharedMemorySize,
                         lstm_smem);

    gemm_partial<<<NB, 512, gemm_smem>>>(x, Wi);
    reduce_stage1<<<dim3(SG / 128, RGROUPS), 128>>>();
    lstm_kernel<<<1, 256, lstm_smem>>>(Wh, bi, bh, out);
}

// round 15
// speedup vs baseline: 1.2426x; 1.0245x over previous
#include <cuda_runtime.h>
#include <cstdint>

#define K_TOTAL 100000
#define KC      704
#define NB      143                           // 142*704 + 32 = 100000 exactly
#define KB      32                            // k per pipeline step
#define SEQ     64
#define G4      200
#define HID     50
#define SG      (SEQ * G4)                    // 12800

#define RGROUPS 16
#define RSPAN   9                             // 16*9 = 144 >= 143

#define XROW    36                            // padded X staging row (floats)

// Scratch (device globals)
__device__ float g_partial[NB * SG];          // 7.3 MB
__device__ float g_p2[RGROUPS * SG];

typedef unsigned long long ull;

__device__ __forceinline__ ull pack2(float a, float b) {
    ull r; asm("mov.b64 %0, {%1, %2};" : "=l"(r) : "f"(a), "f"(b)); return r;
}
__device__ __forceinline__ void fma2(ull& d, ull a, ull b) {
    asm("fma.rn.f32x2 %0, %1, %2, %0;" : "+l"(d) : "l"(a), "l"(b));
}
__device__ __forceinline__ ull add2(ull a, ull b) {
    ull r; asm("add.rn.f32x2 %0, %1, %2;" : "=l"(r) : "l"(a), "l"(b)); return r;
}
__device__ __forceinline__ float lo32(ull v) { return __uint_as_float((unsigned)(v & 0xffffffffu)); }
__device__ __forceinline__ float hi32(ull v) { return __uint_as_float((unsigned)(v >> 32)); }

__device__ __forceinline__ uint32_t smem_u32(const void* p) {
    return (uint32_t)__cvta_generic_to_shared(p);
}
__device__ __forceinline__ void cp_async16(float* smem, const float* gmem) {
    unsigned sa = (unsigned)__cvta_generic_to_shared(smem);
    asm volatile("cp.async.cg.shared.global [%0], [%1], 16;" :: "r"(sa), "l"(gmem));
}
__device__ __forceinline__ void cp_commit() { asm volatile("cp.async.commit_group;"); }
__device__ __forceinline__ void cp_wait2() { asm volatile("cp.async.wait_group 2;"); }

__device__ __forceinline__ void bulk_g2s(uint32_t dst, const void* src, uint32_t bytes,
                                         uint32_t mbar) {
    asm volatile(
        "cp.async.bulk.shared::cta.global.mbarrier::complete_tx::bytes [%0], [%1], %2, [%3];"
        :: "r"(dst), "l"(src), "r"(bytes), "r"(mbar) : "memory");
}
__device__ __forceinline__ void mbar_init(uint32_t mbar, uint32_t cnt) {
    asm volatile("mbarrier.init.shared.b64 [%0], %1;" :: "r"(mbar), "r"(cnt) : "memory");
}
__device__ __forceinline__ void mbar_expect(uint32_t mbar, uint32_t bytes) {
    asm volatile("mbarrier.arrive.expect_tx.shared.b64 _, [%0], %1;"
                 :: "r"(mbar), "r"(bytes) : "memory");
}
__device__ __forceinline__ void mbar_wait(uint32_t mbar, uint32_t phase) {
    asm volatile(
        "{\n\t.reg .pred P;\n\t"
        "W%=: mbarrier.try_wait.parity.acquire.cta.shared::cta.b64 P, [%0], %1, 0x989680;\n\t"
        "@P bra D%=;\n\t"
        "bra W%=;\n\t"
        "D%=:\n\t}"
        :: "r"(mbar), "r"(phase) : "memory");
}

__device__ __forceinline__ uint32_t cvtpack(float hi_val, float lo_val) {
    uint32_t r;
    asm("cvt.rn.bf16x2.f32 %0, %1, %2;" : "=r"(r) : "f"(hi_val), "f"(lo_val));
    return r;
}

__device__ __forceinline__ void mma16816(float* d,
                                         uint32_t a0, uint32_t a1, uint32_t a2, uint32_t a3,
                                         uint32_t b0, uint32_t b1) {
    asm volatile(
        "mma.sync.aligned.m16n8k16.row.col.f32.bf16.bf16.f32 "
        "{%0,%1,%2,%3}, {%4,%5,%6,%7}, {%8,%9}, {%0,%1,%2,%3};"
        : "+f"(d[0]), "+f"(d[1]), "+f"(d[2]), "+f"(d[3])
        : "r"(a0), "r"(a1), "r"(a2), "r"(a3), "r"(b0), "r"(b1));
}

// mslot(j) for j in 0..7 (compile-time table): 2*(j&3) + (j>>2)
__device__ __constant__ const int MSJ[8] = {0, 2, 4, 6, 1, 3, 5, 7};

// ---------------------------------------------------------------------------
// Phase A: split-K tensor-core GEMM (round-14, measured 48.9us) — UNCHANGED.
// ---------------------------------------------------------------------------
__global__ void __launch_bounds__(512, 1) gemm_partial(
    const float* __restrict__ x, const float* __restrict__ Wi)
{
    extern __shared__ float sm[];
    ull*   mbars = (ull*)sm;
    float* stgX = sm + 16;                                  // 4 x 64x36 f32
    float* stgW = stgX + 4 * (64 * XROW);                   // 4 x 32x200 f32
    uint32_t* cXh = (uint32_t*)(stgW + 4 * 6400);           // 2 x 64x18 b32
    uint32_t* cXl = cXh + 2 * 1152;
    uint32_t* cWh = cXl + 2 * 1152;                         // 2 x 200x18 b32
    uint32_t* cWl = cWh + 2 * 3600;

    const int t  = threadIdx.x;
    const int k0 = blockIdx.x * KC;
    const int kcnt = (K_TOTAL - k0 < KC) ? (K_TOTAL - k0) : KC;
    const int S = kcnt / KB;                                // 22 or 1

    const int warp = t >> 5, lane = t & 31;
    const int g = lane >> 2, tq = lane & 3;
    const int mg = warp >> 3;
    const int ng = warp & 7;
    const int NT   = (ng == 0) ? 4 : 3;
    const int nbeg = (ng == 0) ? 0 : (4 + 3 * (ng - 1));

    if (t == 0) {
        #pragma unroll
        for (int b = 0; b < 4; b++) mbar_init(smem_u32(&mbars[b]), 1);
    }
    __syncthreads();

    float acc[2][4][4];
    #pragma unroll
    for (int a = 0; a < 2; a++)
        #pragma unroll
        for (int b = 0; b < 4; b++)
            #pragma unroll
            for (int c = 0; c < 4; c++) acc[a][b][c] = 0.f;

    auto issue_stage = [&](int step) {
        const int b4 = step & 3;
        const int kg = k0 + step * KB;
        if (t == 0) {
            const uint32_t mb = smem_u32(&mbars[b4]);
            mbar_expect(mb, 25600);
            bulk_g2s(smem_u32(stgW + b4 * 6400), Wi + (size_t)kg * G4, 25600, mb);
        }
        {
            float* dX = stgX + b4 * (64 * XROW);
            const int row = t >> 3, q = t & 7;
            cp_async16(dX + row * XROW + q * 4, x + (size_t)row * K_TOTAL + kg + q * 4);
        }
    };

    auto wait_W = [&](int step) {
        mbar_wait(smem_u32(&mbars[step & 3]), (step >> 2) & 1);
    };

    auto convert = [&](int b4, int b2) {
        if (t < 400) {
            const int n0 = t % 200;
            const int half = t / 200;
            const float* sWb = stgW + b4 * 6400 + half * 3200 + n0;
            uint32_t* whb = cWh + b2 * 3600 + n0 * 18 + half * 8;
            uint32_t* wlb = cWl + b2 * 3600 + n0 * 18 + half * 8;
            #pragma unroll
            for (int j = 0; j < 8; j++) {
                const float f0 = sWb[400 * j];
                const float f1 = sWb[400 * j + 200];
                const uint32_t hi = cvtpack(f1, f0);
                const float h0 = __uint_as_float(hi << 16);
                const float h1 = __uint_as_float(hi & 0xFFFF0000u);
                const uint32_t lo = cvtpack(f1 - h1, f0 - h0);
                whb[MSJ[j]] = hi;
                wlb[MSJ[j]] = lo;
            }
        }
        if (t >= 256) {
            const int tx = t - 256;
            const int row = tx >> 2, q = tx & 3;
            const float* sXb = stgX + b4 * (64 * XROW) + row * XROW + 8 * q;
            const int mbase = (q >> 1) * 8 + (q & 1);
            uint32_t* xhb = cXh + b2 * 1152 + row * 18 + mbase;
            uint32_t* xlb = cXl + b2 * 1152 + row * 18 + mbase;
            #pragma unroll
            for (int j = 0; j < 4; j++) {
                const float f0 = sXb[2 * j];
                const float f1 = sXb[2 * j + 1];
                const uint32_t hi = cvtpack(f1, f0);
                const float h0 = __uint_as_float(hi << 16);
                const float h1 = __uint_as_float(hi & 0xFFFF0000u);
                const uint32_t lo = cvtpack(f1 - h1, f0 - h0);
                xhb[2 * j] = hi;
                xlb[2 * j] = lo;
            }
        }
    };

    auto mma_tile = [&](int b2) {
        const uint32_t* xh = cXh + b2 * 1152; const uint32_t* xl = cXl + b2 * 1152;
        const uint32_t* wh = cWh + b2 * 3600; const uint32_t* wl = cWl + b2 * 3600;
        #pragma unroll
        for (int kb = 0; kb < 16; kb += 8) {
            uint2 Ah0[2], Ah1[2], Al0[2], Al1[2];
            #pragma unroll
            for (int m2 = 0; m2 < 2; m2++) {
                const int r0 = (mg * 2 + m2) * 16 + g;
                Ah0[m2] = *(const uint2*)(xh + r0 * 18 + kb + 2 * tq);
                Ah1[m2] = *(const uint2*)(xh + (r0 + 8) * 18 + kb + 2 * tq);
                Al0[m2] = *(const uint2*)(xl + r0 * 18 + kb + 2 * tq);
                Al1[m2] = *(const uint2*)(xl + (r0 + 8) * 18 + kb + 2 * tq);
            }
            #pragma unroll
            for (int i = 0; i < 4; i++) {
                if (i < NT) {
                    const int n = (nbeg + i) * 8 + g;
                    const uint2 Bh = *(const uint2*)(wh + n * 18 + kb + 2 * tq);
                    const uint2 Bl = *(const uint2*)(wl + n * 18 + kb + 2 * tq);
                    #pragma unroll
                    for (int m2 = 0; m2 < 2; m2++) {
                        mma16816(acc[m2][i], Ah0[m2].x, Ah1[m2].x, Ah0[m2].y, Ah1[m2].y, Bh.x, Bh.y);
                        mma16816(acc[m2][i], Ah0[m2].x, Ah1[m2].x, Ah0[m2].y, Ah1[m2].y, Bl.x, Bl.y);
                        mma16816(acc[m2][i], Al0[m2].x, Al1[m2].x, Al0[m2].y, Al1[m2].y, Bh.x, Bh.y);
                    }
                }
            }
        }
    };

    issue_stage(0);
    cp_commit();
    if (S > 1) issue_stage(1);
    cp_commit();
    if (S > 2) issue_stage(2);
    cp_commit();
    cp_wait2();
    wait_W(0);
    __syncthreads();
    convert(0, 0);

    for (int s = 0; s < S; s++) {
        if (s + 3 < S) issue_stage(s + 3);
        cp_commit();
        cp_wait2();
        if (s + 1 < S) wait_W(s + 1);
        __syncthreads();
        if (s + 1 < S) convert((s + 1) & 3, (s + 1) & 1);
        mma_tile(s & 1);
    }

    float* pout = g_partial + (size_t)blockIdx.x * SG;
    #pragma unroll
    for (int m2 = 0; m2 < 2; m2++) {
        const int r0 = (mg * 2 + m2) * 16 + g;
        #pragma unroll
        for (int i = 0; i < 4; i++) {
            if (i < NT) {
                const int col = (nbeg + i) * 8 + 2 * tq;
                *(float2*)(pout + (size_t)r0 * G4 + col)       = make_float2(acc[m2][i][0], acc[m2][i][1]);
                *(float2*)(pout + (size_t)(r0 + 8) * G4 + col) = make_float2(acc[m2][i][2], acc[m2][i][3]);
            }
        }
    }
}

// ---------------------------------------------------------------------------
// Phase B: stage-1 split-K reduce (143 -> 16)
// ---------------------------------------------------------------------------
__global__ void reduce_stage1()
{
    const int idx = blockIdx.x * blockDim.x + threadIdx.x;
    const int grp = blockIdx.y;
    if (idx >= SG) return;
    const int b0   = grp * RSPAN;
    const int bend = (b0 + RSPAN < NB) ? (b0 + RSPAN) : NB;
    float s0 = 0.f, s1 = 0.f, s2 = 0.f, s3 = 0.f;
    int b = b0;
    for (; b + 3 < bend; b += 4) {
        s0 += g_partial[(size_t)(b + 0) * SG + idx];
        s1 += g_partial[(size_t)(b + 1) * SG + idx];
        s2 += g_partial[(size_t)(b + 2) * SG + idx];
        s3 += g_partial[(size_t)(b + 3) * SG + idx];
    }
    for (; b < bend; b++) s0 += g_partial[(size_t)b * SG + idx];
    g_p2[(size_t)grp * SG + idx] = (s0 + s1) + (s2 + s3);
}

// ---------------------------------------------------------------------------
// Phase C: LSTM — quad-per-unit layout. Thread 4u+q computes gate q of unit u
// (weights in 50 regs). Gate exchange via 4 intra-warp shfl.idx (no smem, no
// barrier); activation computed redundantly in all 4 lanes (c in registers);
// h double-buffered in smem; ONE __syncthreads per step.
// ---------------------------------------------------------------------------
__device__ __forceinline__ float tanh_fast(float v) {
    float r; asm("tanh.approx.f32 %0, %1;" : "=f"(r) : "f"(v)); return r;
}
__device__ __forceinline__ float sig_fast(float v) {
    return fmaf(0.5f, tanh_fast(0.5f * v), 0.5f);
}

__global__ void __launch_bounds__(256) lstm_kernel(const float* __restrict__ Wh,
                                                   const float* __restrict__ bi,
                                                   const float* __restrict__ bh,
                                                   float* __restrict__ out)
{
    extern __shared__ float sml[];
    float* gates_s = sml;                 // SG floats (51.2 KB)
    float* hbuf    = sml + SG;            // 2 x 64 floats (double buffer)
    const int t = threadIdx.x;

    // merged reduce (16 partials) + biases -> gates_s (all 8 warps)
    {
        const float4* src = (const float4*)g_p2;
        float4* dst = (float4*)gates_s;
        for (int i4 = t; i4 < SG / 4; i4 += 256) {
            float4 a0 = make_float4(0.f, 0.f, 0.f, 0.f);
            float4 a1 = a0, a2 = a0, a3 = a0;
            #pragma unroll
            for (int b = 0; b < RGROUPS; b += 4) {
                float4 v0 = src[(size_t)(b + 0) * (SG / 4) + i4];
                float4 v1 = src[(size_t)(b + 1) * (SG / 4) + i4];
                float4 v2 = src[(size_t)(b + 2) * (SG / 4) + i4];
                float4 v3 = src[(size_t)(b + 3) * (SG / 4) + i4];
                a0.x += v0.x; a0.y += v0.y; a0.z += v0.z; a0.w += v0.w;
                a1.x += v1.x; a1.y += v1.y; a1.z += v1.z; a1.w += v1.w;
                a2.x += v2.x; a2.y += v2.y; a2.z += v2.z; a2.w += v2.w;
                a3.x += v3.x; a3.y += v3.y; a3.z += v3.z; a3.w += v3.w;
            }
            const int gbase = (i4 * 4) % G4;
            const float4 bv1 = *(const float4*)(bi + gbase);
            const float4 bv2 = *(const float4*)(bh + gbase);
            float4 r;
            r.x = (a0.x + a1.x) + (a2.x + a3.x) + bv1.x + bv2.x;
            r.y = (a0.y + a1.y) + (a2.y + a3.y) + bv1.y + bv2.y;
            r.z = (a0.z + a1.z) + (a2.z + a3.z) + bv1.z + bv2.z;
            r.w = (a0.w + a1.w) + (a2.w + a3.w) + bv1.w + bv2.w;
            dst[i4] = r;
        }
    }

    // quad-per-unit recurrence setup
    const int u = t >> 2;                 // unit 0..49 (t<200)
    const int q = t & 3;                  // gate 0..3
    const bool act = (t < 200);
    const int col = 50 * q + u;           // gate column in [0,200)

    ull wq[25];
    if (act) {
        #pragma unroll
        for (int k2 = 0; k2 < 25; k2++)
            wq[k2] = pack2(Wh[(2 * k2) * G4 + col], Wh[(2 * k2 + 1) * G4 + col]);
    }
    if (t < 128) hbuf[t] = 0.f;
    float c = 0.f, h = 0.f;
    __syncthreads();

    const int lane = t & 31;
    const int qbase = lane & ~3;          // quad base lane

    for (int step = 0; step < SEQ; step++) {
        float d = 0.f;
        if (act) {
            const ull* hu = (const ull*)(hbuf + (step & 1) * 64);
            ull a0 = 0ull, a1 = 0ull, a2 = 0ull, a3 = 0ull;
            #pragma unroll
            for (int k2 = 0; k2 < 24; k2 += 4) {
                fma2(a0, hu[k2],     wq[k2]);
                fma2(a1, hu[k2 + 1], wq[k2 + 1]);
                fma2(a2, hu[k2 + 2], wq[k2 + 2]);
                fma2(a3, hu[k2 + 3], wq[k2 + 3]);
            }
            fma2(a0, hu[24], wq[24]);
            const ull s = add2(add2(a0, a1), add2(a2, a3));
            d = gates_s[step * G4 + col] + lo32(s) + hi32(s);
        }
        // gather the quad's four gate pre-activations (all lanes participate)
        const float gi = __shfl_sync(0xffffffffu, d, qbase + 0);
        const float gf = __shfl_sync(0xffffffffu, d, qbase + 1);
        const float gg = __shfl_sync(0xffffffffu, d, qbase + 2);
        const float go = __shfl_sync(0xffffffffu, d, qbase + 3);
        if (act) {
            const float iv = sig_fast(gi);
            const float fv = sig_fast(gf);
            const float gv = tanh_fast(gg);
            const float ov = sig_fast(go);
            c = fv * c + iv * gv;                     // 4 coherent copies per unit
            h = ov * tanh_fast(c);
            hbuf[((step + 1) & 1) * 64 + u] = h;      // duplicate same-value writes
        }
        __syncthreads();                              // single barrier per step
    }
    if (act && q == 0) out[u] = h;
}

// ---------------------------------------------------------------------------
extern "C" void kernel_launch(void* const* d_in, const int* in_sizes, int n_in,
                              void* d_out, int out_size)
{
    const float* x  = (const float*)d_in[0];
    const float* Wi = (const float*)d_in[1];
    const float* bi = (const float*)d_in[2];
    const float* Wh = (const float*)d_in[3];
    const float* bh = (const float*)d_in[4];
    float* out = (float*)d_out;

    (void)in_sizes; (void)n_in; (void)out_size;

    const int gemm_smem = 16 * 4 + 4 * 64 * XROW * 4 + 4 * 6400 * 4
                        + (2 * 1152 * 2 + 2 * 3600 * 2) * 4;   // ~215.4 KB
    cudaFuncSetAttribute(gemm_partial, cudaFuncAttributeMaxDynamicSharedMemorySize,
                         gemm_smem);
    const int lstm_smem = (SG + 128) * 4 + 64;
    cudaFuncSetAttribute(lstm_kernel, cudaFuncAttributeMaxDynamicSharedMemorySize,
                         lstm_smem);

    gemm_partial<<<NB, 512, gemm_smem>>>(x, Wi);
    reduce_stage1<<<dim3(SG / 128, RGROUPS), 128>>>();
    lstm_kernel<<<1, 256, lstm_smem>>>(Wh, bi, bh, out);
}